// round 16
// baseline (speedup 1.0000x reference)
#include <cuda_runtime.h>
#include <math.h>

// PDHG / Chambolle-Pock TV denoising, persistent kernel, WARP-DECOUPLED.
// P=2, C=1, NX=128, NY=128, NT=8; T=128 iterations.
// CTA = slab of 2 x-rows x 128 y (256 thr). Warp = 32 consecutive y of one row.
// NO __syncthreads in the loop:
//  - intra-CTA (partner row + y-blocks): double-buffered SMEM + per-warp smem
//    seqs (st.release.cta / ld.acquire.cta spin, ~30cyc).
//  - inter-CTA x-halo: 1:1 warp-paired messages; payload (2 slots, 32x32B,
//    coalesced) + seq in one structure; consumer poll reads seq AND payload in
//    the same round -> payload arrives with discovery.
// Own duals q0,q1,q2 + minus-neighbor duals q0m,q1m carried in registers.

#define NTD 8
#define NPB 2
#define NSLAB 64
#define NCTA (NSLAB * NPB)   // 128
#define NTHR 256
#define NW 8

struct __align__(128) Msg {
    float pay[2][32][8];     // 2048 B: slot, lane, t  (coalesced 32B/lane)
    unsigned seq;            // own 128B line
    unsigned pad[31];
};
__device__ Msg g_msg[NCTA][NW];    // ~2.2 MB

// ---- memory-model primitives ----
__device__ __forceinline__ void st_release_gpu(unsigned* p, unsigned v) {
    asm volatile("st.release.gpu.global.u32 [%0], %1;" :: "l"(p), "r"(v) : "memory");
}
__device__ __forceinline__ unsigned ld_acquire_gpu(const unsigned* p) {
    unsigned v;
    asm volatile("ld.acquire.gpu.global.u32 %0, [%1];" : "=r"(v) : "l"(p) : "memory");
    return v;
}
__device__ __forceinline__ void stcg_v4(float* p, float a, float b, float c, float d) {
    asm volatile("st.global.cg.v4.f32 [%0], {%1,%2,%3,%4};"
                 :: "l"(p), "f"(a), "f"(b), "f"(c), "f"(d) : "memory");
}
__device__ __forceinline__ float4 ldcg_v4(const float* p) {
    float4 v;
    asm volatile("ld.global.cg.v4.f32 {%0,%1,%2,%3}, [%4];"
                 : "=f"(v.x), "=f"(v.y), "=f"(v.z), "=f"(v.w) : "l"(p) : "memory");
    return v;
}
__device__ __forceinline__ unsigned smem_u32(const void* p) {
    return (unsigned)__cvta_generic_to_shared(p);
}
__device__ __forceinline__ void sts_release_cta(unsigned a, unsigned v) {
    asm volatile("st.release.cta.shared::cta.u32 [%0], %1;" :: "r"(a), "r"(v) : "memory");
}
__device__ __forceinline__ unsigned lds_acquire_cta(unsigned a) {
    unsigned v;
    asm volatile("ld.acquire.cta.shared::cta.u32 %0, [%1];" : "=r"(v) : "r"(a) : "memory");
    return v;
}

#define LOADP(dst, ptr, off) do { \
    float4 a_ = *reinterpret_cast<const float4*>((ptr) + (off)); \
    float4 b_ = *reinterpret_cast<const float4*>((ptr) + (off) + 4); \
    dst[0]=a_.x; dst[1]=a_.y; dst[2]=a_.z; dst[3]=a_.w; \
    dst[4]=b_.x; dst[5]=b_.y; dst[6]=b_.z; dst[7]=b_.w; } while(0)

#define STOREP(ptr, off, src) do { \
    *reinterpret_cast<float4*>((ptr) + (off))     = make_float4(src[0],src[1],src[2],src[3]); \
    *reinterpret_cast<float4*>((ptr) + (off) + 4) = make_float4(src[4],src[5],src[6],src[7]); } while(0)

#define LOADS(dst, smemrow) do { \
    float4 a_ = *reinterpret_cast<const float4*>(smemrow); \
    float4 b_ = *reinterpret_cast<const float4*>((smemrow) + 4); \
    dst[0]=a_.x; dst[1]=a_.y; dst[2]=a_.z; dst[3]=a_.w; \
    dst[4]=b_.x; dst[5]=b_.y; dst[6]=b_.z; dst[7]=b_.w; } while(0)

extern "C" __global__ void __launch_bounds__(NTHR, 1)
pdhg_persist_kernel(const float* __restrict__ xin,
                    const float* __restrict__ lamin,
                    const float* __restrict__ taup,
                    const float* __restrict__ sigp,
                    const float* __restrict__ thp,
                    const int*   __restrict__ Tp,
                    float* __restrict__ out)
{
    __shared__ float sm_xb[2][NTHR][NTD];     // 16 KB double-buffered xbar
    __shared__ unsigned sm_seq[NW][8];        // per-warp intra seq (32B apart)

    // ---- scalars ----
    const float L    = sqrtf(13.0f);
    const float sig  = (1.0f / (1.0f + expf(-sigp[0]))) / L;
    const float tauv = (1.0f / (1.0f + expf(-taup[0]))) / L;
    const float th   = 1.0f / (1.0f + expf(-thp[0]));
    const float i1s  = 1.0f / (1.0f + sig);

    int T = Tp[0];
    if (T < 1 || T > 65536) {
        float tf = __int_as_float(T);
        T = (int)tf;
        if (T < 1 || T > 65536) T = 128;
    }

    // ---- mapping ----
    const int cta  = blockIdx.x;          // 0..127
    const int pp   = cta >> 6;
    const int s    = cta & 63;            // slab (rows 2s, 2s+1)
    const int tid  = threadIdx.x;
    const int w    = tid >> 5;            // warp 0..7
    const int lane = tid & 31;
    const int r    = w >> 2;              // row in slab
    const int b    = w & 3;               // y-block
    const int y    = (b << 5) + lane;
    const int x    = (s << 1) + r;

    const int pb  = pp << 14;
    const int o   = (pb + (x << 7) + y) << 3;
    const int omx = (pb + (((x - 1) & 127) << 7) + y) << 3;
    const int omy = (pb + (x << 7) + ((y - 1) & 127)) << 3;

    const int pidx = (r << 7) + y;                     // own smem pencil
    const int ppar = ((1 ^ r) << 7) + y;               // partner-row pencil
    const int pyp  = (r << 7) + ((y + 1) & 127);
    const int pym  = (r << 7) + ((y - 1) & 127);

    // ---- remote message pairing (1:1 warps) ----
    Msg* my_msg = &g_msg[cta][w];
    const int nslab = (r == 0) ? ((s + 63) & 63) : ((s + 1) & 63);
    const Msg* cs_msg = &g_msg[(pp << 6) | nslab][((1 ^ r) << 2) + b];

    // base: own msg seq; only this warp's lane0 writes it -> race-free.
    // All seqs advance by exactly T per run -> equal at entry. Wrap-safe diff.
    unsigned base = 0;
    if (lane == 0) base = ld_acquire_gpu(&my_msg->seq);
    base = __shfl_sync(0xffffffffu, base, 0);

    // intra seq addresses: the 3 warps I consume from
    const unsigned a_own = smem_u32(&sm_seq[w][0]);
    const unsigned a_prt = smem_u32(&sm_seq[((1 ^ r) << 2) + b][0]);
    const unsigned a_yp  = smem_u32(&sm_seq[(r << 2) + ((b + 1) & 3)][0]);
    const unsigned a_ym  = smem_u32(&sm_seq[(r << 2) + ((b + 3) & 3)][0]);

    // ---- persistent register state ----
    float xn[8], x0[8], pv[8], q0[8], q1[8], q2[8], xb[8], lam[8], lmx[8], lmy[8];
    float q0m[8], q1m[8];
    LOADP(xn,  xin,   o);
    LOADP(lam, lamin, o);
    LOADP(lmx, lamin, omx);
    LOADP(lmy, lamin, omy);
#pragma unroll
    for (int t = 0; t < 8; t++) {
        x0[t] = xn[t]; pv[t] = xn[t]; xb[t] = xn[t];
        q0[t] = 0.0f;  q1[t] = 0.0f;  q2[t] = 0.0f;
        q0m[t] = 0.0f; q1m[t] = 0.0f;
    }

    // ---- init publish: xbar^0 -> msg slot0 (seq base+1) + smem buf0 (seq 1) --
    {
        float* mp = &my_msg->pay[0][lane][0];
        stcg_v4(mp,     xb[0], xb[1], xb[2], xb[3]);
        stcg_v4(mp + 4, xb[4], xb[5], xb[6], xb[7]);
        __syncwarp();
        if (lane == 0) st_release_gpu(&my_msg->seq, base + 1u);
#pragma unroll
        for (int t = 0; t < 8; t++) sm_xb[0][pidx][t] = xb[t];
        if (lane == 0) sm_seq[w][0] = 1u;
    }
    __syncthreads();   // one-time: smem seq/buffers initialized for all warps

    // ---- main loop (no block barrier inside) ----
    for (int it = 0; it < T; ++it) {
        const int cur = it & 1;
        const unsigned need = (unsigned)(it + 1);

        // 1. pre-poll compute from own registers only (q2-dual + p-prox)
        float q2n[8], pnv[8];
#pragma unroll
        for (int t = 0; t < 8; t++) {
            float v2 = q2[t] + sig * (xb[(t + 1) & 7] - xb[t]);
            q2n[t] = fminf(fmaxf(v2, -lam[t]), lam[t]);
            pnv[t] = (pv[t] + sig * (xb[t] - xn[t])) * i1s;
        }

        // 2. intra-CTA waits: 3 lanes spin on the 3 producer warps' seqs.
        //    seq >= it+1 also proves those warps finished it-1 -> safe to
        //    overwrite buffer cur^1 later this iteration.
        if (lane == 0) { while (lds_acquire_cta(a_prt) < need) { } }
        if (lane == 1) { while (lds_acquire_cta(a_yp)  < need) { } }
        if (lane == 2) { while (lds_acquire_cta(a_ym)  < need) { } }
        __syncwarp();

        // 3. smem halos + halo-side duals that don't need the remote pencil
        float prt[8], bpy[8], bmy[8];
        LOADS(prt, &sm_xb[cur][ppar][0]);
        LOADS(bpy, &sm_xb[cur][pyp][0]);
        LOADS(bmy, &sm_xb[cur][pym][0]);

        float q1n[8], q1mn[8], qx[8];
#pragma unroll
        for (int t = 0; t < 8; t++) {
            float v1  = q1[t] + sig * (bpy[t] - xb[t]);
            q1n[t]  = fminf(fmaxf(v1, -lam[t]), lam[t]);
            float v1m = q1m[t] + sig * (xb[t] - bmy[t]);
            q1mn[t] = fminf(fmaxf(v1m, -lmy[t]), lmy[t]);
        }
        if (r == 0) {
#pragma unroll
            for (int t = 0; t < 8; t++) {        // bpx = partner row (smem)
                float v0 = q0[t] + sig * (prt[t] - xb[t]);
                qx[t] = fminf(fmaxf(v0, -lam[t]), lam[t]);       // q0n
            }
        } else {
#pragma unroll
            for (int t = 0; t < 8; t++) {        // bmx = partner row (smem)
                float v0m = q0m[t] + sig * (xb[t] - prt[t]);
                qx[t] = fminf(fmaxf(v0m, -lmx[t]), lmx[t]);      // q0mn
            }
        }

        // 4. remote poll: seq + payload in the same round (payload rides).
        //    seq >= it+1 proves partner finished it-1 -> slot (it+1)&1 free.
        float rem[8];
        {
            const float* cp = &cs_msg->pay[cur][lane][0];
            unsigned sv; float4 u, v;
            do {
                sv = ld_acquire_gpu(const_cast<unsigned*>(&cs_msg->seq));
                u  = ldcg_v4(cp);
                v  = ldcg_v4(cp + 4);
            } while (sv - base < need);
            rem[0]=u.x; rem[1]=u.y; rem[2]=u.z; rem[3]=u.w;
            rem[4]=v.x; rem[5]=v.y; rem[6]=v.z; rem[7]=v.w;
        }

        // 5. remote-side dual, divergence, primal update
#pragma unroll
        for (int t = 0; t < 8; t++) {
            float q0n, q0mn;
            if (r == 0) {
                q0n  = qx[t];
                float v0m = q0m[t] + sig * (xb[t] - rem[t]);
                q0mn = fminf(fmaxf(v0m, -lmx[t]), lmx[t]);
            } else {
                q0mn = qx[t];
                float v0 = q0[t] + sig * (rem[t] - xb[t]);
                q0n  = fminf(fmaxf(v0, -lam[t]), lam[t]);
            }
            float dv = (q0mn - q0n) + (q1mn[t] - q1n[t])
                     + (q2n[(t + 7) & 7] - q2n[t]);

            float x1  = x0[t] - tauv * (pnv[t] + dv);
            float xbn = x1 + th * (x1 - x0[t]);

            x0[t] = x1; pv[t] = pnv[t];
            q0[t] = q0n; q1[t] = q1n[t]; q0m[t] = q0mn; q1m[t] = q1mn[t];
            q2[t] = q2n[t];
            xb[t] = xbn;
        }

        // 6. publish: remote first (longest chain), then smem; per-warp seqs.
        if (it != T - 1) {
            float* mp = &my_msg->pay[(it + 1) & 1][lane][0];
            stcg_v4(mp,     xb[0], xb[1], xb[2], xb[3]);
            stcg_v4(mp + 4, xb[4], xb[5], xb[6], xb[7]);
            __syncwarp();
            if (lane == 0) st_release_gpu(&my_msg->seq, base + (unsigned)(it + 2));

#pragma unroll
            for (int t = 0; t < 8; t++) sm_xb[cur ^ 1][pidx][t] = xb[t];
            __syncwarp();
            if (lane == 0) sts_release_cta(a_own, (unsigned)(it + 2));
        }
    }

    // ---- output ----
    STOREP(out, o, x0);
}

extern "C" void kernel_launch(void* const* d_in, const int* in_sizes, int n_in,
                              void* d_out, int out_size) {
    const float* x    = (const float*)d_in[0];
    const float* lam  = (const float*)d_in[1];
    const float* tau  = (const float*)d_in[2];
    const float* sigm = (const float*)d_in[3];
    const float* thet = (const float*)d_in[4];
    const int*   Tp   = (const int*)d_in[5];
    float* out = (float*)d_out;
    pdhg_persist_kernel<<<NCTA, NTHR>>>(x, lam, tau, sigm, thet, Tp, out);
}

// round 17
// speedup vs baseline: 1.7123x; 1.7123x over previous
#include <cuda_runtime.h>
#include <math.h>

// PDHG / Chambolle-Pock TV denoising, persistent kernel, SLAB decomposition.
// == R8 structure (best: 213us) with two critical-edge cuts ==
// CTA = slab of 2 x-rows x full 128 y (256 threads, 1 pencil/thread).
// y-halo + partner-row: intra-CTA via double-buffered SMEM (+1 block barrier).
// x-halo: dense g_xbar publish; PER-ROW flags released after a 128-thread
// NAMED barrier (bar.sync r+1) so the remote chain never waits on the other
// row or the smem path. Poll = lane0-only, one word (the R8 discipline).
// All smem-side compute hoisted ABOVE the poll; register-only compute placed
// after the remote LDG to hide its latency.

#define NTD 8
#define NPB 2
#define NPIX (NPB * 128 * 128 * NTD)   // 262144
#define NSLAB 64
#define NCTA (NSLAB * NPB)              // 128
#define NTHR 256

__device__ __align__(256) float g_xbar[2][NPIX];
// one flag per (cta,row), each on its own 128B line
__device__ __align__(128) unsigned g_rflags[NCTA * 2 * 32];

__device__ __forceinline__ void st_release_gpu(unsigned* p, unsigned v) {
    asm volatile("st.release.gpu.global.u32 [%0], %1;" :: "l"(p), "r"(v) : "memory");
}
__device__ __forceinline__ unsigned ld_acquire_gpu(const unsigned* p) {
    unsigned v;
    asm volatile("ld.acquire.gpu.global.u32 %0, [%1];" : "=r"(v) : "l"(p) : "memory");
    return v;
}
__device__ __forceinline__ void bar_row(int r) {   // named barrier, 128 thr
    asm volatile("bar.sync %0, 128;" :: "r"(r + 1) : "memory");
}

#define LOADP_CG(dst, ptr, off) do { \
    float4 a_ = __ldcg(reinterpret_cast<const float4*>((ptr) + (off))); \
    float4 b_ = __ldcg(reinterpret_cast<const float4*>((ptr) + (off) + 4)); \
    dst[0]=a_.x; dst[1]=a_.y; dst[2]=a_.z; dst[3]=a_.w; \
    dst[4]=b_.x; dst[5]=b_.y; dst[6]=b_.z; dst[7]=b_.w; } while(0)

#define LOADP(dst, ptr, off) do { \
    float4 a_ = *reinterpret_cast<const float4*>((ptr) + (off)); \
    float4 b_ = *reinterpret_cast<const float4*>((ptr) + (off) + 4); \
    dst[0]=a_.x; dst[1]=a_.y; dst[2]=a_.z; dst[3]=a_.w; \
    dst[4]=b_.x; dst[5]=b_.y; dst[6]=b_.z; dst[7]=b_.w; } while(0)

#define STOREP_CG(ptr, off, src) do { \
    __stcg(reinterpret_cast<float4*>((ptr) + (off)),     make_float4(src[0],src[1],src[2],src[3])); \
    __stcg(reinterpret_cast<float4*>((ptr) + (off) + 4), make_float4(src[4],src[5],src[6],src[7])); } while(0)

#define STOREP(ptr, off, src) do { \
    *reinterpret_cast<float4*>((ptr) + (off))     = make_float4(src[0],src[1],src[2],src[3]); \
    *reinterpret_cast<float4*>((ptr) + (off) + 4) = make_float4(src[4],src[5],src[6],src[7]); } while(0)

#define LOADS(dst, smemrow) do { \
    float4 a_ = *reinterpret_cast<const float4*>(smemrow); \
    float4 b_ = *reinterpret_cast<const float4*>((smemrow) + 4); \
    dst[0]=a_.x; dst[1]=a_.y; dst[2]=a_.z; dst[3]=a_.w; \
    dst[4]=b_.x; dst[5]=b_.y; dst[6]=b_.z; dst[7]=b_.w; } while(0)

extern "C" __global__ void __launch_bounds__(NTHR, 1)
pdhg_persist_kernel(const float* __restrict__ xin,
                    const float* __restrict__ lamin,
                    const float* __restrict__ taup,
                    const float* __restrict__ sigp,
                    const float* __restrict__ thp,
                    const int*   __restrict__ Tp,
                    float* __restrict__ out)
{
    __shared__ float sm_xb[2][NTHR][NTD];   // 16 KB, double-buffered xbar

    // ---- scalars ----
    const float L    = sqrtf(13.0f);
    const float sig  = (1.0f / (1.0f + expf(-sigp[0]))) / L;
    const float tauv = (1.0f / (1.0f + expf(-taup[0]))) / L;
    const float th   = 1.0f / (1.0f + expf(-thp[0]));
    const float i1s  = 1.0f / (1.0f + sig);

    int T = Tp[0];
    if (T < 1 || T > 65536) {
        float tf = __int_as_float(T);
        T = (int)tf;
        if (T < 1 || T > 65536) T = 128;
    }

    // ---- mapping (identical to R8) ----
    const int cta = blockIdx.x;
    const int pp  = cta >> 6;
    const int s   = cta & 63;             // slab (rows 2s, 2s+1)
    const int tid = threadIdx.x;
    const int r   = tid >> 7;             // row in slab
    const int y   = tid & 127;
    const int x   = (s << 1) + r;
    const int yp  = (y + 1) & 127, ym = (y - 1) & 127;

    const int pb = pp << 14;
    const int o  = (pb + (x << 7) + y) << 3;
    const int omx = (pb + (((x - 1) & 127) << 7) + y) << 3;
    const int omy = (pb + (x << 7) + ym) << 3;

    const int xr = (r == 0) ? ((x - 1) & 127) : ((x + 1) & 127);
    const int orem = (pb + (xr << 7) + y) << 3;

    const int partner = (r == 0) ? (128 + y) : y;
    const int iyp = (r << 7) + yp;
    const int iym = (r << 7) + ym;

    // ---- per-row flags ----
    // my row's flag; consumer row polls the PRODUCING row's flag:
    // row0 of slab s consumes row1 of slab s-1; row1 consumes row0 of slab s+1.
    unsigned* my_flag = &g_rflags[(cta * 2 + r) * 32];
    const unsigned* nbr_flag;
    {
        int nslab = (r == 0) ? ((s + 63) & 63) : ((s + 1) & 63);
        int ncta  = (pp << 6) | nslab;
        nbr_flag = &g_rflags[(ncta * 2 + (1 ^ r)) * 32];
    }
    // base: all flags advance by exactly T per run -> equal at entry.
    // Read by every thread BEFORE the init release (ordered by the named bar
    // + __syncthreads below). Wrap-safe unsigned diff everywhere.
    const unsigned base = ld_acquire_gpu(my_flag);

    // ---- persistent register state ----
    float xn[8], x0[8], pv[8], q0[8], q1[8], q2[8], xb[8], lam[8], lmx[8], lmy[8];
    float q0m[8], q1m[8];
    LOADP(xn,  xin,   o);
    LOADP(lam, lamin, o);
    LOADP(lmx, lamin, omx);
    LOADP(lmy, lamin, omy);
#pragma unroll
    for (int t = 0; t < 8; t++) {
        x0[t] = xn[t]; pv[t] = xn[t]; xb[t] = xn[t];
        q0[t] = 0.0f;  q1[t] = 0.0f;  q2[t] = 0.0f;
        q0m[t] = 0.0f; q1m[t] = 0.0f;
    }

    // init publish: global row stores -> named bar(row) -> row flag; then smem.
    STOREP_CG(g_xbar[0], o, xb);
    bar_row(r);
    if ((tid & 127) == 0) st_release_gpu(my_flag, base + 1u);
#pragma unroll
    for (int t = 0; t < 8; t++) sm_xb[0][tid][t] = xb[t];
    __syncthreads();

    // ---- main loop ----
    for (int it = 0; it < T; ++it) {
        const int cur = it & 1;

        // 1. smem halos (ready since last block barrier) + smem-side duals --
        //    ALL hoisted above the poll: they never wait on the remote flag.
        float prt[8], bpy[8], bmy[8];
        LOADS(prt, &sm_xb[cur][partner][0]);
        LOADS(bpy, &sm_xb[cur][iyp][0]);
        LOADS(bmy, &sm_xb[cur][iym][0]);

        float q1n[8], q1mn[8], qx[8];
#pragma unroll
        for (int t = 0; t < 8; t++) {
            float v1  = q1[t] + sig * (bpy[t] - xb[t]);
            q1n[t]  = fminf(fmaxf(v1, -lam[t]), lam[t]);
            float v1m = q1m[t] + sig * (xb[t] - bmy[t]);
            q1mn[t] = fminf(fmaxf(v1m, -lmy[t]), lmy[t]);
        }
        if (r == 0) {
#pragma unroll
            for (int t = 0; t < 8; t++) {       // bpx = partner row (smem)
                float v0 = q0[t] + sig * (prt[t] - xb[t]);
                qx[t] = fminf(fmaxf(v0, -lam[t]), lam[t]);      // q0n
            }
        } else {
#pragma unroll
            for (int t = 0; t < 8; t++) {       // bmx = partner row (smem)
                float v0m = q0m[t] + sig * (xb[t] - prt[t]);
                qx[t] = fminf(fmaxf(v0m, -lmx[t]), lmx[t]);     // q0mn
            }
        }

        // 2. discovery: lane0-only poll of ONE word (the R8 discipline).
        //    flag >= it+1 also proves the partner row finished it-1, the last
        //    reader of buffer cur^1 we overwrite below.
        if ((tid & 31) == 0) {
            const unsigned need = (unsigned)(it + 1);
            while (ld_acquire_gpu(nbr_flag) - base < need) { }
        }
        __syncwarp();

        // 3. remote pencil LDG issued now ...
        float rem[8];
        LOADP_CG(rem, g_xbar[cur], orem);

        // 4. ... hidden behind register-only compute (q2-dual + p-prox)
        float q2n[8], pnv[8];
#pragma unroll
        for (int t = 0; t < 8; t++) {
            float v2 = q2[t] + sig * (xb[(t + 1) & 7] - xb[t]);
            q2n[t] = fminf(fmaxf(v2, -lam[t]), lam[t]);
            pnv[t] = (pv[t] + sig * (xb[t] - xn[t])) * i1s;
        }

        // 5. remote-side dual, divergence, update
#pragma unroll
        for (int t = 0; t < 8; t++) {
            float q0n, q0mn;
            if (r == 0) {
                q0n  = qx[t];
                float v0m = q0m[t] + sig * (xb[t] - rem[t]);
                q0mn = fminf(fmaxf(v0m, -lmx[t]), lmx[t]);
            } else {
                q0mn = qx[t];
                float v0 = q0[t] + sig * (rem[t] - xb[t]);
                q0n  = fminf(fmaxf(v0, -lam[t]), lam[t]);
            }
            float dv = (q0mn - q0n) + (q1mn[t] - q1n[t])
                     + (q2n[(t + 7) & 7] - q2n[t]);

            float x1  = x0[t] - tauv * (pnv[t] + dv);
            float xbn = x1 + th * (x1 - x0[t]);

            x0[t] = x1; pv[t] = pnv[t];
            q0[t] = q0n; q1[t] = q1n[t]; q0m[t] = q0mn; q1m[t] = q1mn[t];
            q2[t] = q2n[t];
            xb[t] = xbn;
        }

        if (it != T - 1) {
            // 6. remote chain FIRST: row global stores -> named bar(row) ->
            //    row-leader releases row flag. Other row & smem not involved.
            STOREP_CG(g_xbar[cur ^ 1], o, xb);
            bar_row(r);
            if ((tid & 127) == 0)
                st_release_gpu(my_flag, base + (unsigned)(it + 2));

            // 7. smem publish + block barrier (off the remote chain)
#pragma unroll
            for (int t = 0; t < 8; t++) sm_xb[cur ^ 1][tid][t] = xb[t];
            __syncthreads();
        }
    }

    // ---- output ----
    STOREP(out, o, x0);
}

extern "C" void kernel_launch(void* const* d_in, const int* in_sizes, int n_in,
                              void* d_out, int out_size) {
    const float* x    = (const float*)d_in[0];
    const float* lam  = (const float*)d_in[1];
    const float* tau  = (const float*)d_in[2];
    const float* sigm = (const float*)d_in[3];
    const float* thet = (const float*)d_in[4];
    const int*   Tp   = (const int*)d_in[5];
    float* out = (float*)d_out;
    pdhg_persist_kernel<<<NCTA, NTHR>>>(x, lam, tau, sigm, thet, Tp, out);
}